// round 1
// baseline (speedup 1.0000x reference)
#include <cuda_runtime.h>
#include <cstdint>
#include <math.h>

#define DEV_INLINE __device__ __forceinline__

// ---------------------------------------------------------------------------
// Problem constants
// ---------------------------------------------------------------------------
#define BB 8
#define SS 2048
#define DD 1024
#define MTOT (BB * SS)   // 16384

// ---------------------------------------------------------------------------
// Scratch (allocation-free rule: __device__ globals)
// ---------------------------------------------------------------------------
__device__ float g_Q[(size_t)BB * SS * DD];
__device__ float g_K[(size_t)BB * SS * DD];
__device__ float g_V[(size_t)BB * SS * DD];
__device__ float g_P[(size_t)BB * SS * SS];
__device__ float g_Y[(size_t)BB * SS * DD];

// ---------------------------------------------------------------------------
// TF32 helpers
// ---------------------------------------------------------------------------
DEV_INLINE uint32_t f2tf32(float x) {
    uint32_t r;
    asm("cvt.rna.tf32.f32 %0, %1;" : "=r"(r) : "f"(x));
    return r;
}

DEV_INLINE void mma_tf32(float* d, const uint32_t* a, const uint32_t* b) {
    asm volatile(
        "mma.sync.aligned.m16n8k8.row.col.f32.tf32.tf32.f32 "
        "{%0,%1,%2,%3}, {%4,%5,%6,%7}, {%8,%9}, {%0,%1,%2,%3};\n"
        : "+f"(d[0]), "+f"(d[1]), "+f"(d[2]), "+f"(d[3])
        : "r"(a[0]), "r"(a[1]), "r"(a[2]), "r"(a[3]),
          "r"(b[0]), "r"(b[1]));
}

// ---------------------------------------------------------------------------
// Generic TF32 tensor-core GEMM: C = alpha * A @ op(B), optional ReLU.
//   A: M x K row-major.
//   BT=false: B is K x N row-major.   BT=true: B is N x K row-major (B^T).
//   C: M x N row-major.
//   blockIdx.z batches via byte-element strides sAz/sBz/sCz.
// Block tile 128x128, K-tile 16, 256 threads, warp grid 2(M) x 4(N),
// each warp 64x32 via m16n8k8 fragments. Double-buffered smem.
// All dims assumed multiples of tile sizes (true for this problem).
// ---------------------------------------------------------------------------
template <bool BT, bool RELU>
__global__ void __launch_bounds__(256)
gemm_tf32(const float* __restrict__ A, const float* __restrict__ Bm,
          float* __restrict__ C,
          int M, int N, int K, float alpha,
          size_t sAz, size_t sBz, size_t sCz)
{
    A  += blockIdx.z * sAz;
    Bm += blockIdx.z * sBz;
    C  += blockIdx.z * sCz;

    const int tid  = threadIdx.x;
    const int warp = tid >> 5;
    const int lane = tid & 31;
    const int wm   = warp & 1;        // 0..1  (M dir, 64 rows each)
    const int wn   = warp >> 1;       // 0..3  (N dir, 32 cols each)
    const int grp  = lane >> 2;       // 0..7
    const int tig  = lane & 3;        // 0..3
    const int bm   = blockIdx.y;
    const int bn   = blockIdx.x;

    const int lda = K;
    const int ldb = BT ? K : N;

    // A / (B in BT mode): [row][k] with row stride 20 -> conflict-free frags.
    // B normal mode: [k][n] with row stride 132 -> float4 stores aligned, ~2-way frag reads.
    __shared__ uint32_t As[2][128 * 20];
    __shared__ uint32_t Bs[2][BT ? (128 * 20) : (16 * 132)];

    float acc[4][4][4] = {};
    float4 ra[2], rb[2];

    const int nk = K >> 4;

    // ---- prologue: tile 0 directly into smem ----
    {
#pragma unroll
        for (int it = 0; it < 2; it++) {
            int lin = tid + it * 256;
            int row = lin >> 2, c4 = lin & 3;
            float4 v = *(const float4*)(A + (size_t)(bm * 128 + row) * lda + c4 * 4);
            uint32_t* dst = &As[0][row * 20 + c4 * 4];
            dst[0] = f2tf32(v.x); dst[1] = f2tf32(v.y);
            dst[2] = f2tf32(v.z); dst[3] = f2tf32(v.w);
        }
        if (BT) {
#pragma unroll
            for (int it = 0; it < 2; it++) {
                int lin = tid + it * 256;
                int row = lin >> 2, c4 = lin & 3;
                float4 v = *(const float4*)(Bm + (size_t)(bn * 128 + row) * ldb + c4 * 4);
                uint32_t* dst = &Bs[0][row * 20 + c4 * 4];
                dst[0] = f2tf32(v.x); dst[1] = f2tf32(v.y);
                dst[2] = f2tf32(v.z); dst[3] = f2tf32(v.w);
            }
        } else {
#pragma unroll
            for (int it = 0; it < 2; it++) {
                int lin = tid + it * 256;
                int k = lin >> 5, n4 = lin & 31;
                float4 v = *(const float4*)(Bm + (size_t)k * ldb + bn * 128 + n4 * 4);
                uint32_t* dst = &Bs[0][k * 132 + n4 * 4];
                dst[0] = f2tf32(v.x); dst[1] = f2tf32(v.y);
                dst[2] = f2tf32(v.z); dst[3] = f2tf32(v.w);
            }
        }
    }
    __syncthreads();

    for (int kt = 0; kt < nk; kt++) {
        const int buf = kt & 1;
        const bool more = (kt + 1 < nk);

        // ---- prefetch next tile into registers ----
        if (more) {
            const int k0 = (kt + 1) * 16;
#pragma unroll
            for (int it = 0; it < 2; it++) {
                int lin = tid + it * 256;
                int row = lin >> 2, c4 = lin & 3;
                ra[it] = *(const float4*)(A + (size_t)(bm * 128 + row) * lda + k0 + c4 * 4);
            }
            if (BT) {
#pragma unroll
                for (int it = 0; it < 2; it++) {
                    int lin = tid + it * 256;
                    int row = lin >> 2, c4 = lin & 3;
                    rb[it] = *(const float4*)(Bm + (size_t)(bn * 128 + row) * ldb + k0 + c4 * 4);
                }
            } else {
#pragma unroll
                for (int it = 0; it < 2; it++) {
                    int lin = tid + it * 256;
                    int k = lin >> 5, n4 = lin & 31;
                    rb[it] = *(const float4*)(Bm + (size_t)(k0 + k) * ldb + bn * 128 + n4 * 4);
                }
            }
        }

        // ---- compute on current buffer ----
#pragma unroll
        for (int ks = 0; ks < 2; ks++) {
            const int kb = ks * 8;
            uint32_t af[4][4];
            uint32_t bfr[4][2];
#pragma unroll
            for (int mt = 0; mt < 4; mt++) {
                const int m0 = wm * 64 + mt * 16 + grp;
                const uint32_t* as = &As[buf][0];
                af[mt][0] = as[m0 * 20 + kb + tig];
                af[mt][1] = as[(m0 + 8) * 20 + kb + tig];
                af[mt][2] = as[m0 * 20 + kb + tig + 4];
                af[mt][3] = as[(m0 + 8) * 20 + kb + tig + 4];
            }
#pragma unroll
            for (int nt = 0; nt < 4; nt++) {
                const int n0 = wn * 32 + nt * 8 + grp;
                if (BT) {
                    bfr[nt][0] = Bs[buf][n0 * 20 + kb + tig];
                    bfr[nt][1] = Bs[buf][n0 * 20 + kb + tig + 4];
                } else {
                    bfr[nt][0] = Bs[buf][(kb + tig) * 132 + n0];
                    bfr[nt][1] = Bs[buf][(kb + tig + 4) * 132 + n0];
                }
            }
#pragma unroll
            for (int mt = 0; mt < 4; mt++)
#pragma unroll
                for (int nt = 0; nt < 4; nt++)
                    mma_tf32(acc[mt][nt], af[mt], bfr[nt]);
        }

        // ---- store prefetched tile into other buffer ----
        if (more) {
            const int nb = buf ^ 1;
#pragma unroll
            for (int it = 0; it < 2; it++) {
                int lin = tid + it * 256;
                int row = lin >> 2, c4 = lin & 3;
                uint32_t* dst = &As[nb][row * 20 + c4 * 4];
                dst[0] = f2tf32(ra[it].x); dst[1] = f2tf32(ra[it].y);
                dst[2] = f2tf32(ra[it].z); dst[3] = f2tf32(ra[it].w);
            }
            if (BT) {
#pragma unroll
                for (int it = 0; it < 2; it++) {
                    int lin = tid + it * 256;
                    int row = lin >> 2, c4 = lin & 3;
                    uint32_t* dst = &Bs[nb][row * 20 + c4 * 4];
                    dst[0] = f2tf32(rb[it].x); dst[1] = f2tf32(rb[it].y);
                    dst[2] = f2tf32(rb[it].z); dst[3] = f2tf32(rb[it].w);
                }
            } else {
#pragma unroll
                for (int it = 0; it < 2; it++) {
                    int lin = tid + it * 256;
                    int k = lin >> 5, n4 = lin & 31;
                    uint32_t* dst = &Bs[nb][k * 132 + n4 * 4];
                    dst[0] = f2tf32(rb[it].x); dst[1] = f2tf32(rb[it].y);
                    dst[2] = f2tf32(rb[it].z); dst[3] = f2tf32(rb[it].w);
                }
            }
        }
        __syncthreads();
    }

    // ---- epilogue ----
    float* Cw = C + (size_t)(bm * 128 + wm * 64) * N + bn * 128 + wn * 32;
#pragma unroll
    for (int mt = 0; mt < 4; mt++) {
#pragma unroll
        for (int nt = 0; nt < 4; nt++) {
            const int r = mt * 16 + grp;
            const int c = nt * 8 + tig * 2;
            float2 v0, v1;
            v0.x = acc[mt][nt][0] * alpha;
            v0.y = acc[mt][nt][1] * alpha;
            v1.x = acc[mt][nt][2] * alpha;
            v1.y = acc[mt][nt][3] * alpha;
            if (RELU) {
                v0.x = fmaxf(v0.x, 0.f); v0.y = fmaxf(v0.y, 0.f);
                v1.x = fmaxf(v1.x, 0.f); v1.y = fmaxf(v1.y, 0.f);
            }
            *(float2*)(Cw + (size_t)r * N + c)       = v0;
            *(float2*)(Cw + (size_t)(r + 8) * N + c) = v1;
        }
    }
}

// ---------------------------------------------------------------------------
// Row softmax with additive mask: p[j] = softmax_j( p[j] + mask[b][j] * -1e9 )
// One block (256 threads) per row of 2048; values stay in registers.
// ---------------------------------------------------------------------------
__global__ void __launch_bounds__(256)
softmax_mask(float* __restrict__ P, const int* __restrict__ mask)
{
    const int row = blockIdx.x;        // 0 .. B*S-1
    const int b   = row >> 11;         // row / 2048
    float* p = P + (size_t)row * SS;
    const int* mrow = mask + (size_t)b * SS;

    const int tid  = threadIdx.x;
    const int lane = tid & 31;
    const int warp = tid >> 5;
    __shared__ float red[8];

    float v[8];
    float mx = -INFINITY;
#pragma unroll
    for (int i = 0; i < 8; i++) {
        const int j = tid + i * 256;
        float x = p[j];
        if (mrow[j]) x -= 1.0e9f;
        v[i] = x;
        mx = fmaxf(mx, x);
    }
#pragma unroll
    for (int o = 16; o; o >>= 1) mx = fmaxf(mx, __shfl_xor_sync(0xffffffffu, mx, o));
    if (lane == 0) red[warp] = mx;
    __syncthreads();
    mx = red[0];
#pragma unroll
    for (int w = 1; w < 8; w++) mx = fmaxf(mx, red[w]);

    float s = 0.f;
#pragma unroll
    for (int i = 0; i < 8; i++) {
        const float e = __expf(v[i] - mx);
        v[i] = e;
        s += e;
    }
    __syncthreads();                   // red[] reuse
#pragma unroll
    for (int o = 16; o; o >>= 1) s += __shfl_xor_sync(0xffffffffu, s, o);
    if (lane == 0) red[warp] = s;
    __syncthreads();
    s = red[0];
#pragma unroll
    for (int w = 1; w < 8; w++) s += red[w];

    const float inv = 1.0f / s;
#pragma unroll
    for (int i = 0; i < 8; i++) p[tid + i * 256] = v[i] * inv;
}

// ---------------------------------------------------------------------------
// Launch
// ---------------------------------------------------------------------------
extern "C" void kernel_launch(void* const* d_in, const int* in_sizes, int n_in,
                              void* d_out, int out_size)
{
    (void)in_sizes; (void)n_in; (void)out_size;

    const float* x1      = (const float*)d_in[0];
    const float* x2      = (const float*)d_in[1];
    const int*   maskSeq = (const int*)  d_in[2];
    const float* wq      = (const float*)d_in[3];
    const float* wk      = (const float*)d_in[4];
    const float* wv      = (const float*)d_in[5];
    const float* wo      = (const float*)d_in[6];
    float* out = (float*)d_out;

    float *Q, *Kp, *V, *P, *Y;
    cudaGetSymbolAddress((void**)&Q,  g_Q);
    cudaGetSymbolAddress((void**)&Kp, g_K);
    cudaGetSymbolAddress((void**)&V,  g_V);
    cudaGetSymbolAddress((void**)&P,  g_P);
    cudaGetSymbolAddress((void**)&Y,  g_Y);

    const dim3 blk(256);
    const float scale = 0.03125f;      // 1024^-0.5

    // Projections: (16384 x 1024) = X (16384 x 1024) @ W (1024 x 1024)
    gemm_tf32<false, false><<<dim3(DD / 128, MTOT / 128, 1), blk>>>(
        x1, wq, Q, MTOT, DD, DD, scale, 0, 0, 0);
    gemm_tf32<false, false><<<dim3(DD / 128, MTOT / 128, 1), blk>>>(
        x2, wk, Kp, MTOT, DD, DD, 1.f, 0, 0, 0);
    gemm_tf32<false, false><<<dim3(DD / 128, MTOT / 128, 1), blk>>>(
        x2, wv, V, MTOT, DD, DD, 1.f, 0, 0, 0);

    // Scores: per batch (2048 x 2048) = Q @ K^T
    gemm_tf32<true, false><<<dim3(SS / 128, SS / 128, BB), blk>>>(
        Q, Kp, P, SS, SS, DD, 1.f,
        (size_t)SS * DD, (size_t)SS * DD, (size_t)SS * SS);

    // Mask + softmax (in place)
    softmax_mask<<<BB * SS, 256>>>(P, maskSeq);

    // Y = P @ V with fused ReLU, per batch
    gemm_tf32<false, true><<<dim3(DD / 128, SS / 128, BB), blk>>>(
        P, V, Y, SS, DD, SS, 1.f,
        (size_t)SS * SS, (size_t)SS * DD, (size_t)SS * DD);

    // Output projection
    gemm_tf32<false, false><<<dim3(DD / 128, MTOT / 128, 1), blk>>>(
        Y, wo, out, MTOT, DD, DD, 1.f, 0, 0, 0);
}